// round 12
// baseline (speedup 1.0000x reference)
#include <cuda_runtime.h>
#include <stdint.h>

// Problem shape (fixed by the dataset)
constexpr int B       = 4;
constexpr int N       = 32768;
constexpr int NQ      = 2048;
constexpr int K       = 16;
constexpr int QSTRIDE = N / NQ;   // 16

constexpr int TILE    = 1024;          // candidate points per smem tile
constexpr int PAIRS   = TILE / 2;      // 2 candidates per lane-step
constexpr int WPB     = 4;             // warps per block
constexpr int QPW     = 2;             // queries per warp (packed in f32x2)
constexpr int THREADS = WPB * 32;      // 128
constexpr int QPB     = WPB * QPW;     // 8 queries per block
constexpr int BLOCKS_PER_BATCH = NQ / QPB;  // 256

typedef unsigned long long u64;
typedef unsigned int u32;

constexpr u64 KEY_INF = ~0ULL;
constexpr u32 FULL    = 0xffffffffu;

// ---- packed 2xfp32 helpers (Blackwell f32x2; .rn per half == __fadd_rn) ----
__device__ __forceinline__ u64 add2(u64 a, u64 b) {
    u64 r; asm("add.rn.f32x2 %0, %1, %2;" : "=l"(r) : "l"(a), "l"(b)); return r;
}
__device__ __forceinline__ u64 mul2(u64 a, u64 b) {
    u64 r; asm("mul.rn.f32x2 %0, %1, %2;" : "=l"(r) : "l"(a), "l"(b)); return r;
}
__device__ __forceinline__ u64 pk(u32 lo, u32 hi) {
    u64 r; asm("mov.b64 %0, {%1, %2};" : "=l"(r) : "r"(lo), "r"(hi)); return r;
}
__device__ __forceinline__ void unpk(u32& lo, u32& hi, u64 v) {
    asm("mov.b64 {%0, %1}, %2;" : "=r"(lo), "=r"(hi) : "l"(v));
}

// Insert up to 32 candidate keys (nk, invalid lanes = KEY_INF, mask m) into
// the warp-distributed sorted list L (lane i holds element i, ascending).
__device__ __forceinline__ void warp_insert(u64& L, u64 nk, u32 m, int lane) {
    if (__popc(m) <= 2) {
        while (m) {                       // 1-2 keys: distributed shift-insert
            const int src = __ffs(m) - 1;
            m &= m - 1;
            const u64 k  = __shfl_sync(FULL, nk, src);
            const u64 up = __shfl_up_sync(FULL, L, 1);
            if (k < L) L = (lane > 0 && k < up) ? up : k;
        }
    } else {
        // Bitonic sort 32 candidates ascending.
#pragma unroll
        for (int k2 = 2; k2 <= 32; k2 <<= 1) {
#pragma unroll
            for (int j2 = k2 >> 1; j2 >= 1; j2 >>= 1) {
                const u64 o = __shfl_xor_sync(FULL, nk, j2);
                const bool takemin = ((lane & j2) == 0) == ((lane & k2) == 0);
                const bool pl = nk < o;
                nk = (pl == takemin) ? nk : o;
            }
        }
        // Old (asc) vs new reversed (desc): min keeps 32 smallest (bitonic),
        // then clean-up merge.
        const u64 r = __shfl_sync(FULL, nk, 31 - lane);
        L = (L < r) ? L : r;
#pragma unroll
        for (int j2 = 16; j2 >= 1; j2 >>= 1) {
            const u64 o = __shfl_xor_sync(FULL, L, j2);
            const bool takemin = ((lane & j2) == 0);
            const bool pl = L < o;
            L = (pl == takemin) ? L : o;
        }
    }
}

// Exact sub-insert of one (query, candidate): build the u64 key, exact
// lexicographic test against the CURRENT threshold, merge, refresh.
__device__ __forceinline__ void try_insert(u64& L, u64& T, u32& Thi,
                                           u32 dbits, int cidx, int lane) {
    const u64 ck = pk((u32)cidx, dbits);     // hi = distance bits, lo = idx
    const bool v = ck < T;                   // exact (d asc, idx asc)
    const u32 m = __ballot_sync(FULL, v);
    if (m) {
        warp_insert(L, v ? ck : KEY_INF, m, lane);
        T   = __shfl_sync(FULL, L, K - 1);
        Thi = (u32)(T >> 32);
    }
}

// One warp handles TWO queries, packed into f32x2 halves (q0 = lo, q1 = hi).
// Each lane processes 2 candidates per step from a pre-negated, pre-duplicated
// smem layout, so the whole distance computation is packed adds/muls with no
// pack/unpack movs in the hot loop. Distances are bit-exact fp32 (q + (-p),
// ((dx^2+dy^2)+dz^2), round-to-nearest per half), so the u64 key order is
// exactly jax.lax.top_k's (d asc, idx asc).
__global__ __launch_bounds__(THREADS, 7)
void knn_kernel(const float* __restrict__ xyz, float* __restrict__ out) {
    // Per candidate pair (c0, c1): A=(-x0,-x0,-y0,-y0) B=(-z0,-z0,-x1,-x1)
    //                              C=(-y1,-y1,-z1,-z1)   (24 B / candidate)
    __shared__ float4 sA[PAIRS], sB[PAIRS], sC[PAIRS];

    const int lane  = threadIdx.x & 31;
    const int warp  = threadIdx.x >> 5;
    const int batch = blockIdx.x >> 8;                      // / BLOCKS_PER_BATCH
    const int q0    = (blockIdx.x & (BLOCKS_PER_BATCH - 1)) * QPB + warp * QPW;

    const float* __restrict__ base = xyz + (size_t)batch * N * 3;

    const float qx0 = base[(q0 + 0) * QSTRIDE * 3 + 0];
    const float qy0 = base[(q0 + 0) * QSTRIDE * 3 + 1];
    const float qz0 = base[(q0 + 0) * QSTRIDE * 3 + 2];
    const float qx1 = base[(q0 + 1) * QSTRIDE * 3 + 0];
    const float qy1 = base[(q0 + 1) * QSTRIDE * 3 + 1];
    const float qz1 = base[(q0 + 1) * QSTRIDE * 3 + 2];

    const u64 qx01 = pk(__float_as_uint(qx0), __float_as_uint(qx1));
    const u64 qy01 = pk(__float_as_uint(qy0), __float_as_uint(qy1));
    const u64 qz01 = pk(__float_as_uint(qz0), __float_as_uint(qz1));

    u64 L0 = KEY_INF, L1 = KEY_INF;        // distributed sorted lists
    u64 T0 = KEY_INF, T1 = KEY_INF;        // 16th-best keys
    u32 T0h = 0xffffffffu, T1h = 0xffffffffu;  // their distance bits

    for (int t = 0; t < N; t += TILE) {
        __syncthreads();
        for (int i = threadIdx.x; i < PAIRS; i += THREADS) {
            const float* __restrict__ p = base + (size_t)(t + 2 * i) * 3;
            const float x0 = p[0], y0 = p[1], z0 = p[2];
            const float x1 = p[3], y1 = p[4], z1 = p[5];
            sA[i] = make_float4(-x0, -x0, -y0, -y0);
            sB[i] = make_float4(-z0, -z0, -x1, -x1);
            sC[i] = make_float4(-y1, -y1, -z1, -z1);
        }
        __syncthreads();

        const ulonglong2* __restrict__ A = (const ulonglong2*)sA;
        const ulonglong2* __restrict__ Bv = (const ulonglong2*)sB;
        const ulonglong2* __restrict__ C = (const ulonglong2*)sC;

#pragma unroll 4
        for (int s = 0; s < PAIRS / 32; ++s) {
            const int i = s * 32 + lane;
            const ulonglong2 a = A[i];    // (-x0,-x0) (-y0,-y0)
            const ulonglong2 bv = Bv[i];  // (-z0,-z0) (-x1,-x1)
            const ulonglong2 c = C[i];    // (-y1,-y1) (-z1,-z1)

            // Candidate 0 vs both queries (packed halves).
            const u64 dxa = add2(qx01, a.x);
            const u64 dya = add2(qy01, a.y);
            const u64 dza = add2(qz01, bv.x);
            const u64 da  = add2(add2(mul2(dxa, dxa), mul2(dya, dya)),
                                 mul2(dza, dza));
            // Candidate 1.
            const u64 dxb = add2(qx01, bv.y);
            const u64 dyb = add2(qy01, c.x);
            const u64 dzb = add2(qz01, c.y);
            const u64 db  = add2(add2(mul2(dxb, dxb), mul2(dyb, dyb)),
                                 mul2(dzb, dzb));

            u32 d0a, d1a, d0b, d1b;
            unpk(d0a, d1a, da);
            unpk(d0b, d1b, db);

            // Distances are >= 0, so float order == unsigned bit order.
            const bool trig = (d0a <= T0h) | (d1a <= T1h) |
                              (d0b <= T0h) | (d1b <= T1h);
            if (__any_sync(FULL, trig)) {
                const int ca = t + 2 * i;      // candidate 0 global index
                try_insert(L0, T0, T0h, d0a, ca,     lane);
                try_insert(L0, T0, T0h, d0b, ca + 1, lane);
                try_insert(L1, T1, T1h, d1a, ca,     lane);
                try_insert(L1, T1, T1h, d1b, ca + 1, lane);
            }
        }
    }

    // Output 0: idx (B, NQ, K, 1) as fp32 (values < 2^15, exact).
    // Output 1: pts (B, NQ, 3) fp32.
    float* __restrict__ out_idx = out;
    float* __restrict__ out_pts = out + (size_t)B * NQ * K;

    const int qg0 = batch * NQ + q0;
    if (lane < K) {
        out_idx[(size_t)(qg0 + 0) * K + lane] = (float)(u32)(L0 & 0xffffffffu);
        out_idx[(size_t)(qg0 + 1) * K + lane] = (float)(u32)(L1 & 0xffffffffu);
    }
    if (lane == 0) {
        out_pts[(size_t)(qg0 + 0) * 3 + 0] = qx0;
        out_pts[(size_t)(qg0 + 0) * 3 + 1] = qy0;
        out_pts[(size_t)(qg0 + 0) * 3 + 2] = qz0;
        out_pts[(size_t)(qg0 + 1) * 3 + 0] = qx1;
        out_pts[(size_t)(qg0 + 1) * 3 + 1] = qy1;
        out_pts[(size_t)(qg0 + 1) * 3 + 2] = qz1;
    }
}

extern "C" void kernel_launch(void* const* d_in, const int* in_sizes, int n_in,
                              void* d_out, int out_size) {
    (void)in_sizes; (void)n_in; (void)out_size;
    const float* xyz = (const float*)d_in[0];
    float* out = (float*)d_out;

    const int grid = B * BLOCKS_PER_BATCH;   // 1024 blocks
    knn_kernel<<<grid, THREADS>>>(xyz, out);
}